// round 2
// baseline (speedup 1.0000x reference)
#include <cuda_runtime.h>
#include <math.h>

// Problem constants
#define Bsz  2
#define Ssz  2048
#define Dsz  1024
#define Hsz  16
#define DKsz 64
#define Mtot (Bsz * Ssz)   // 4096
#define Ntot Dsz           // 1024
#define Ktot Dsz           // 1024

// Scratch (device globals: allocation-free)
__device__ float g_qh[Bsz * Hsz * Ssz * DKsz];   // [B,H,S,DK]
__device__ float g_kh[Bsz * Hsz * Ssz * DKsz];
__device__ float g_vh[Bsz * Hsz * Ssz * DKsz];
__device__ float g_att[Bsz * Ssz * Dsz];         // [B,S,D]

// ---------------------------------------------------------------------------
// GEMM: out = X[M,K] @ W[N,K]^T + bias[N]
// 128x128 block tile, BK=8, 256 threads, 8x8 per-thread microtile.
// OUT_HEADS=1: scatter to [B,H,S,DK] head layout; 0: plain [M,N].
// ---------------------------------------------------------------------------
template <int OUT_HEADS>
__global__ __launch_bounds__(256, 2) void gemm_bias_kernel(
    const float* __restrict__ X, const float* __restrict__ W,
    const float* __restrict__ bias, float* __restrict__ out)
{
    __shared__ float As[8][128];
    __shared__ float Bs[8][128];

    const int tid = threadIdx.x;
    const int tx = tid & 15;          // 0..15 (N dir)
    const int ty = tid >> 4;          // 0..15 (M dir)
    const int bm = blockIdx.y * 128;
    const int bn = blockIdx.x * 128;

    const int lr = tid >> 1;          // 0..127
    const int lc = (tid & 1) * 4;     // 0 or 4

    const float* Xp = X + (size_t)(bm + lr) * Ktot + lc;
    const float* Wp = W + (size_t)(bn + lr) * Ktot + lc;

    float acc[8][8];
#pragma unroll
    for (int i = 0; i < 8; i++)
#pragma unroll
        for (int j = 0; j < 8; j++) acc[i][j] = 0.0f;

    for (int k0 = 0; k0 < Ktot; k0 += 8) {
        float4 av = *(const float4*)(Xp + k0);
        float4 bv = *(const float4*)(Wp + k0);
        As[lc + 0][lr] = av.x; As[lc + 1][lr] = av.y;
        As[lc + 2][lr] = av.z; As[lc + 3][lr] = av.w;
        Bs[lc + 0][lr] = bv.x; Bs[lc + 1][lr] = bv.y;
        Bs[lc + 2][lr] = bv.z; Bs[lc + 3][lr] = bv.w;
        __syncthreads();

#pragma unroll
        for (int kk = 0; kk < 8; kk++) {
            float a[8], b[8];
            *(float4*)&a[0] = *(const float4*)&As[kk][ty * 4];
            *(float4*)&a[4] = *(const float4*)&As[kk][ty * 4 + 64];
            *(float4*)&b[0] = *(const float4*)&Bs[kk][tx * 4];
            *(float4*)&b[4] = *(const float4*)&Bs[kk][tx * 4 + 64];
#pragma unroll
            for (int i = 0; i < 8; i++)
#pragma unroll
                for (int j = 0; j < 8; j++)
                    acc[i][j] += a[i] * b[j];
        }
        __syncthreads();
    }

    // Epilogue: add bias, scatter
#pragma unroll
    for (int i = 0; i < 8; i++) {
        const int mo = (i < 4) ? (ty * 4 + i) : (64 + ty * 4 + (i - 4));
        const int m = bm + mo;
#pragma unroll
        for (int j = 0; j < 8; j++) {
            const int no = (j < 4) ? (tx * 4 + j) : (64 + tx * 4 + (j - 4));
            const int n = bn + no;
            const float v = acc[i][j] + bias[n];
            if (OUT_HEADS == 0) {
                out[(size_t)m * Ntot + n] = v;
            } else {
                const int b  = m >> 11;     // / 2048
                const int s  = m & 2047;
                const int h  = n >> 6;      // / 64
                const int dk = n & 63;
                out[(((size_t)(b * Hsz + h) * Ssz) + s) * DKsz + dk] = v;
            }
        }
    }
}

// ---------------------------------------------------------------------------
// Flash attention, causal. One CTA per (bh, q-tile of 64 rows).
// 256 threads = 16x16 grid, 4x4 microtiles for both S=QK^T and O=PV.
// smem: Qt (Q^T, prescaled), KtPt (K^T, reused for P^T), Vs. 48KB total.
// ---------------------------------------------------------------------------
__global__ __launch_bounds__(256, 2) void flash_attn_kernel(
    const float* __restrict__ Q, const float* __restrict__ K,
    const float* __restrict__ V, float* __restrict__ O)
{
    __shared__ float Qt[64][64];     // Qt[d][r]
    __shared__ float KtPt[64][64];   // Kt[d][c], then Pt[c][r]
    __shared__ float Vs[64][64];     // Vs[c][d]

    const int tid = threadIdx.x;
    const int tx = tid & 15;         // cols
    const int ty = tid >> 4;         // rows
    const int qi = blockIdx.x;       // q tile index (0..31)
    const int bh = blockIdx.y;       // 0..31 (b*H + h)

    const float* Qb = Q + ((size_t)bh * Ssz + qi * 64) * DKsz;

    // Load Q tile transposed + prescale by 1/sqrt(DK)=0.125
#pragma unroll
    for (int q4 = 0; q4 < 4; q4++) {
        const int r  = (tid >> 4) + q4 * 16;
        const int d4 = (tid & 15) * 4;
        float4 qv = *(const float4*)(Qb + r * DKsz + d4);
        Qt[d4 + 0][r] = qv.x * 0.125f;
        Qt[d4 + 1][r] = qv.y * 0.125f;
        Qt[d4 + 2][r] = qv.z * 0.125f;
        Qt[d4 + 3][r] = qv.w * 0.125f;
    }

    float acc[4][4];
#pragma unroll
    for (int i = 0; i < 4; i++)
#pragma unroll
        for (int j = 0; j < 4; j++) acc[i][j] = 0.0f;
    float mrow[4], lrow[4];
#pragma unroll
    for (int i = 0; i < 4; i++) { mrow[i] = -INFINITY; lrow[i] = 0.0f; }

    for (int j = 0; j <= qi; j++) {
        __syncthreads();  // previous iter's KtPt/Vs reads done; Qt load done (iter 0)

        // Load K tile transposed, V tile natural
        const float* Kb = K + ((size_t)bh * Ssz + j * 64) * DKsz;
        const float* Vb = V + ((size_t)bh * Ssz + j * 64) * DKsz;
#pragma unroll
        for (int q4 = 0; q4 < 4; q4++) {
            const int c  = (tid >> 4) + q4 * 16;
            const int d4 = (tid & 15) * 4;
            float4 kv = *(const float4*)(Kb + c * DKsz + d4);
            KtPt[d4 + 0][c] = kv.x;
            KtPt[d4 + 1][c] = kv.y;
            KtPt[d4 + 2][c] = kv.z;
            KtPt[d4 + 3][c] = kv.w;
        }
        {
            float4* Vs4 = (float4*)&Vs[0][0];
            const float4* Vb4 = (const float4*)Vb;
#pragma unroll
            for (int q4 = 0; q4 < 4; q4++)
                Vs4[tid + q4 * 256] = Vb4[tid + q4 * 256];
        }
        __syncthreads();

        // S = Q K^T (scaled)
        float s[4][4];
#pragma unroll
        for (int i = 0; i < 4; i++)
#pragma unroll
            for (int jj = 0; jj < 4; jj++) s[i][jj] = 0.0f;
#pragma unroll 8
        for (int d = 0; d < 64; d++) {
            float a[4], b[4];
            *(float4*)a = *(const float4*)&Qt[d][ty * 4];
            *(float4*)b = *(const float4*)&KtPt[d][tx * 4];
#pragma unroll
            for (int i = 0; i < 4; i++)
#pragma unroll
                for (int jj = 0; jj < 4; jj++)
                    s[i][jj] += a[i] * b[jj];
        }

        // Causal mask on diagonal block
        if (j == qi) {
#pragma unroll
            for (int i = 0; i < 4; i++) {
                const int rg = ty * 4 + i;
#pragma unroll
                for (int jj = 0; jj < 4; jj++) {
                    const int cg = tx * 4 + jj;
                    if (cg > rg) s[i][jj] = -INFINITY;
                }
            }
        }

        // Online softmax (reduce across the 16 lanes sharing a row: xor 1,2,4,8)
#pragma unroll
        for (int i = 0; i < 4; i++) {
            float mx = fmaxf(fmaxf(s[i][0], s[i][1]), fmaxf(s[i][2], s[i][3]));
#pragma unroll
            for (int o = 8; o >= 1; o >>= 1)
                mx = fmaxf(mx, __shfl_xor_sync(0xffffffffu, mx, o));
            const float mnew  = fmaxf(mrow[i], mx);
            const float alpha = __expf(mrow[i] - mnew);
            float sum = 0.0f;
#pragma unroll
            for (int jj = 0; jj < 4; jj++) {
                const float p = __expf(s[i][jj] - mnew);
                s[i][jj] = p;
                sum += p;
            }
#pragma unroll
            for (int o = 8; o >= 1; o >>= 1)
                sum += __shfl_xor_sync(0xffffffffu, sum, o);
            lrow[i] = lrow[i] * alpha + sum;
            mrow[i] = mnew;
#pragma unroll
            for (int jj = 0; jj < 4; jj++) acc[i][jj] *= alpha;
        }

        __syncthreads();  // everyone done reading KtPt as K^T

        // Store P transposed into KtPt: Pt[c][r]
#pragma unroll
        for (int i = 0; i < 4; i++)
#pragma unroll
            for (int jj = 0; jj < 4; jj++)
                KtPt[tx * 4 + jj][ty * 4 + i] = s[i][jj];
        __syncthreads();

        // O += P V
#pragma unroll 8
        for (int c = 0; c < 64; c++) {
            float a[4], b[4];
            *(float4*)a = *(const float4*)&KtPt[c][ty * 4];
            *(float4*)b = *(const float4*)&Vs[c][tx * 4];
#pragma unroll
            for (int i = 0; i < 4; i++)
#pragma unroll
                for (int jj = 0; jj < 4; jj++)
                    acc[i][jj] += a[i] * b[jj];
        }
    }

    // Epilogue: normalize + write to [B,S,D] with head interleave
    const int b = bh >> 4;      // / 16
    const int h = bh & 15;
#pragma unroll
    for (int i = 0; i < 4; i++) {
        const float inv = 1.0f / lrow[i];
        const int srow = qi * 64 + ty * 4 + i;
#pragma unroll
        for (int jj = 0; jj < 4; jj++) {
            const int dv = tx * 4 + jj;
            O[((size_t)b * Ssz + srow) * Dsz + h * DKsz + dv] = acc[i][jj] * inv;
        }
    }
}

// ---------------------------------------------------------------------------
extern "C" void kernel_launch(void* const* d_in, const int* in_sizes, int n_in,
                              void* d_out, int out_size)
{
    const float* q   = (const float*)d_in[0];
    const float* k   = (const float*)d_in[1];
    const float* v   = (const float*)d_in[2];
    // d_in[3] = mask (causal, recomputed analytically)
    const float* w_q = (const float*)d_in[4];
    const float* b_q = (const float*)d_in[5];
    const float* w_k = (const float*)d_in[6];
    const float* b_k = (const float*)d_in[7];
    const float* w_v = (const float*)d_in[8];
    const float* b_v = (const float*)d_in[9];
    const float* w_o = (const float*)d_in[10];
    const float* b_o = (const float*)d_in[11];
    float* out = (float*)d_out;

    float *qh, *kh, *vh, *att;
    cudaGetSymbolAddress((void**)&qh,  g_qh);
    cudaGetSymbolAddress((void**)&kh,  g_kh);
    cudaGetSymbolAddress((void**)&vh,  g_vh);
    cudaGetSymbolAddress((void**)&att, g_att);

    dim3 gGemm(Ntot / 128, Mtot / 128);  // (8, 32)
    dim3 bGemm(256);

    gemm_bias_kernel<1><<<gGemm, bGemm>>>(q, w_q, b_q, qh);
    gemm_bias_kernel<1><<<gGemm, bGemm>>>(k, w_k, b_k, kh);
    gemm_bias_kernel<1><<<gGemm, bGemm>>>(v, w_v, b_v, vh);

    dim3 gFlash(Ssz / 64, Bsz * Hsz);    // (32, 32)
    flash_attn_kernel<<<gFlash, 256>>>(qh, kh, vh, att);

    gemm_bias_kernel<0><<<gGemm, bGemm>>>(att, w_o, b_o, out);
}

// round 4
// speedup vs baseline: 1.4490x; 1.4490x over previous
#include <cuda_runtime.h>
#include <cuda_bf16.h>
#include <math.h>
#include <stdint.h>

// Problem constants
#define Bsz  2
#define Ssz  2048
#define Dsz  1024
#define Hsz  16
#define DKsz 64
#define Mtot (Bsz * Ssz)   // 4096
#define Ntot Dsz           // 1024
#define Ktot Dsz           // 1024

// ---------------------------------------------------------------------------
// Scratch (device globals: allocation-free)
// ---------------------------------------------------------------------------
__device__ float g_qh[Bsz * Hsz * Ssz * DKsz];   // [B,H,S,DK]
__device__ float g_kh[Bsz * Hsz * Ssz * DKsz];
__device__ float g_vh[Bsz * Hsz * Ssz * DKsz];
__device__ float g_att[Bsz * Ssz * Dsz];         // [B,S,D]

// bf16 hi/lo splits
__device__ __nv_bfloat16 g_q_hi[Mtot * Ktot],  g_q_lo[Mtot * Ktot];
__device__ __nv_bfloat16 g_k_hi[Mtot * Ktot],  g_k_lo[Mtot * Ktot];
__device__ __nv_bfloat16 g_v_hi[Mtot * Ktot],  g_v_lo[Mtot * Ktot];
__device__ __nv_bfloat16 g_att_hi[Mtot * Ktot], g_att_lo[Mtot * Ktot];
__device__ __nv_bfloat16 g_wq_hi[Dsz * Dsz], g_wq_lo[Dsz * Dsz];
__device__ __nv_bfloat16 g_wk_hi[Dsz * Dsz], g_wk_lo[Dsz * Dsz];
__device__ __nv_bfloat16 g_wv_hi[Dsz * Dsz], g_wv_lo[Dsz * Dsz];
__device__ __nv_bfloat16 g_wo_hi[Dsz * Dsz], g_wo_lo[Dsz * Dsz];

// ---------------------------------------------------------------------------
// Helpers
// ---------------------------------------------------------------------------
__device__ __forceinline__ uint32_t smem_to_u32(const void* smem_ptr) {
    uint32_t addr;
    asm("{ .reg .u64 tmp; cvta.to.shared.u64 tmp, %1; cvt.u32.u64 %0, tmp; }"
        : "=r"(addr) : "l"(smem_ptr));
    return addr;
}

__device__ __forceinline__ void cp_async16(uint32_t dst, const void* src) {
    asm volatile("cp.async.cg.shared.global [%0], [%1], 16;" :: "r"(dst), "l"(src));
}
__device__ __forceinline__ void cp_async_commit() {
    asm volatile("cp.async.commit_group;");
}
template <int N>
__device__ __forceinline__ void cp_async_wait() {
    asm volatile("cp.async.wait_group %0;" :: "n"(N));
}

__device__ __forceinline__ void ldsm_x4(uint32_t& r0, uint32_t& r1, uint32_t& r2,
                                        uint32_t& r3, uint32_t addr) {
    asm volatile("ldmatrix.sync.aligned.m8n8.x4.shared.b16 {%0,%1,%2,%3}, [%4];"
                 : "=r"(r0), "=r"(r1), "=r"(r2), "=r"(r3) : "r"(addr));
}

__device__ __forceinline__ void mma16816(float& d0, float& d1, float& d2, float& d3,
                                         uint32_t a0, uint32_t a1, uint32_t a2, uint32_t a3,
                                         uint32_t b0, uint32_t b1) {
    asm volatile(
        "mma.sync.aligned.m16n8k16.row.col.f32.bf16.bf16.f32 "
        "{%0,%1,%2,%3}, {%4,%5,%6,%7}, {%8,%9}, {%0,%1,%2,%3};"
        : "+f"(d0), "+f"(d1), "+f"(d2), "+f"(d3)
        : "r"(a0), "r"(a1), "r"(a2), "r"(a3), "r"(b0), "r"(b1));
}

// ---------------------------------------------------------------------------
// fp32 -> (hi, lo) bf16 split
// ---------------------------------------------------------------------------
__global__ void split_kernel(const float* __restrict__ x,
                             __nv_bfloat16* __restrict__ hi,
                             __nv_bfloat16* __restrict__ lo, int n4)
{
    int i = blockIdx.x * blockDim.x + threadIdx.x;
    if (i >= n4) return;
    float4 v = ((const float4*)x)[i];
    __nv_bfloat16 h0 = __float2bfloat16_rn(v.x);
    __nv_bfloat16 h1 = __float2bfloat16_rn(v.y);
    __nv_bfloat16 h2 = __float2bfloat16_rn(v.z);
    __nv_bfloat16 h3 = __float2bfloat16_rn(v.w);
    __nv_bfloat16 l0 = __float2bfloat16_rn(v.x - __bfloat162float(h0));
    __nv_bfloat16 l1 = __float2bfloat16_rn(v.y - __bfloat162float(h1));
    __nv_bfloat16 l2 = __float2bfloat16_rn(v.z - __bfloat162float(h2));
    __nv_bfloat16 l3 = __float2bfloat16_rn(v.w - __bfloat162float(h3));
    __nv_bfloat162* hp = (__nv_bfloat162*)hi;
    __nv_bfloat162* lp = (__nv_bfloat162*)lo;
    hp[i * 2 + 0] = __nv_bfloat162(h0, h1);
    hp[i * 2 + 1] = __nv_bfloat162(h2, h3);
    lp[i * 2 + 0] = __nv_bfloat162(l0, l1);
    lp[i * 2 + 1] = __nv_bfloat162(l2, l3);
}

// ---------------------------------------------------------------------------
// bf16x3 GEMM via mma.sync: out[M,N] = A[M,K] @ B[N,K]^T + bias
// CTA 128x128, BK=32, 8 warps (2x4), warp tile 64x32, double-buffered cp.async.
// smem tile layout: rows of 32 bf16 (64B), 16B chunks swizzled c ^= (row>>1)&3.
// ---------------------------------------------------------------------------
#define BK 32
#define NC (Ktot / BK)                 // 32 chunks
#define TILE_B (128 * BK * 2)          // 8192 bytes per bf16 tile
#define BUF_B  (4 * TILE_B)            // Ahi, Alo, Bhi, Blo = 32 KB
#define GEMM_SMEM (2 * BUF_B)          // 64 KB

__device__ __forceinline__ uint32_t sw_off(int row, int c) {
    return (uint32_t)(row * 64 + ((c ^ ((row >> 1) & 3)) << 4));
}

__device__ __forceinline__ void prefetch_chunk(
    uint32_t sbase, int buf,
    const __nv_bfloat16* Ahi, const __nv_bfloat16* Alo,
    const __nv_bfloat16* Bhi, const __nv_bfloat16* Blo,
    int bm, int bn, int k0, int tid)
{
    const __nv_bfloat16* srcs[4] = { Ahi, Alo, Bhi, Blo };
    const int r0[4] = { bm, bm, bn, bn };
    uint32_t base = sbase + buf * BUF_B;
#pragma unroll
    for (int t = 0; t < 4; t++) {
#pragma unroll
        for (int it = 0; it < 2; it++) {
            int seg = tid + it * 256;          // 0..511
            int row = seg >> 2;                // 0..127
            int c   = seg & 3;                 // 16B chunk
            const void* src = srcs[t] + (size_t)(r0[t] + row) * Ktot + k0 + c * 8;
            cp_async16(base + t * TILE_B + sw_off(row, c), src);
        }
    }
}

template <int OUT_HEADS>
__global__ __launch_bounds__(256, 2) void gemm_tc_kernel(
    const __nv_bfloat16* __restrict__ Ahi, const __nv_bfloat16* __restrict__ Alo,
    const __nv_bfloat16* __restrict__ Bhi, const __nv_bfloat16* __restrict__ Blo,
    const float* __restrict__ bias, float* __restrict__ out)
{
    extern __shared__ __align__(128) char smem[];
    const uint32_t sbase = smem_to_u32(smem);

    const int tid = threadIdx.x;
    const int wid = tid >> 5;
    const int lid = tid & 31;
    const int wr = wid >> 2;          // 0..1  (m dir, 64 rows)
    const int wc = wid & 3;           // 0..3  (n dir, 32 cols)
    const int bm = blockIdx.y * 128;
    const int bn = blockIdx.x * 128;

    float acc[4][4][4];
#pragma unroll
    for (int mi = 0; mi < 4; mi++)
#pragma unroll
        for (int ni = 0; ni < 4; ni++)
#pragma unroll
            for (int r = 0; r < 4; r++) acc[mi][ni][r] = 0.0f;

    prefetch_chunk(sbase, 0, Ahi, Alo, Bhi, Blo, bm, bn, 0, tid);
    cp_async_commit();

    for (int c = 0; c < NC; c++) {
        if (c + 1 < NC) {
            prefetch_chunk(sbase, (c + 1) & 1, Ahi, Alo, Bhi, Blo,
                           bm, bn, (c + 1) * BK, tid);
            cp_async_commit();
            cp_async_wait<1>();
        } else {
            cp_async_wait<0>();
        }
        __syncthreads();

        const uint32_t buf = sbase + (c & 1) * BUF_B;
        const uint32_t sAhi = buf + 0 * TILE_B;
        const uint32_t sAlo = buf + 1 * TILE_B;
        const uint32_t sBhi = buf + 2 * TILE_B;
        const uint32_t sBlo = buf + 3 * TILE_B;

#pragma unroll
        for (int ks = 0; ks < 2; ks++) {
            // B fragments: 2 ldmatrix.x4 per precision, each covers 2 n-tiles
            uint32_t bh[4][2], bl[4][2];
#pragma unroll
            for (int p = 0; p < 2; p++) {
                const int nrow = wc * 32 + p * 16 + (lid & 15);
                const int kc = ks * 2 + (lid >> 4);
                uint32_t r0, r1, r2, r3;
                ldsm_x4(r0, r1, r2, r3, sBhi + sw_off(nrow, kc));
                bh[p * 2][0] = r0; bh[p * 2 + 1][0] = r1;
                bh[p * 2][1] = r2; bh[p * 2 + 1][1] = r3;
                ldsm_x4(r0, r1, r2, r3, sBlo + sw_off(nrow, kc));
                bl[p * 2][0] = r0; bl[p * 2 + 1][0] = r1;
                bl[p * 2][1] = r2; bl[p * 2 + 1][1] = r3;
            }
#pragma unroll
            for (int mi = 0; mi < 4; mi++) {
                const int mrow = wr * 64 + mi * 16 + (lid & 15);
                const int kc = ks * 2 + (lid >> 4);
                uint32_t ah0, ah1, ah2, ah3, al0, al1, al2, al3;
                ldsm_x4(ah0, ah1, ah2, ah3, sAhi + sw_off(mrow, kc));
                ldsm_x4(al0, al1, al2, al3, sAlo + sw_off(mrow, kc));
#pragma unroll
                for (int ni = 0; ni < 4; ni++) {
                    float* d = acc[mi][ni];
                    mma16816(d[0], d[1], d[2], d[3],
                             ah0, ah1, ah2, ah3, bh[ni][0], bh[ni][1]);
                    mma16816(d[0], d[1], d[2], d[3],
                             ah0, ah1, ah2, ah3, bl[ni][0], bl[ni][1]);
                    mma16816(d[0], d[1], d[2], d[3],
                             al0, al1, al2, al3, bh[ni][0], bh[ni][1]);
                }
            }
        }
        __syncthreads();
    }

    // Epilogue: bias + (optional) head scatter
#pragma unroll
    for (int mi = 0; mi < 4; mi++) {
#pragma unroll
        for (int ni = 0; ni < 4; ni++) {
#pragma unroll
            for (int half = 0; half < 2; half++) {
                const int m = bm + wr * 64 + mi * 16 + (lid >> 2) + half * 8;
                const int n = bn + wc * 32 + ni * 8 + 2 * (lid & 3);
                const float v0 = acc[mi][ni][half * 2 + 0] + bias[n];
                const float v1 = acc[mi][ni][half * 2 + 1] + bias[n + 1];
                if (OUT_HEADS == 0) {
                    *(float2*)&out[(size_t)m * Ntot + n] = make_float2(v0, v1);
                } else {
                    const int b  = m >> 11;
                    const int s  = m & 2047;
                    const int h  = n >> 6;
                    const int dk = n & 63;
                    *(float2*)&out[(((size_t)(b * Hsz + h) * Ssz) + s) * DKsz + dk] =
                        make_float2(v0, v1);
                }
            }
        }
    }
}

// ---------------------------------------------------------------------------
// Flash attention, causal (unchanged SIMT fp32)
// ---------------------------------------------------------------------------
__global__ __launch_bounds__(256, 2) void flash_attn_kernel(
    const float* __restrict__ Q, const float* __restrict__ K,
    const float* __restrict__ V, float* __restrict__ O)
{
    __shared__ float Qt[64][64];
    __shared__ float KtPt[64][64];
    __shared__ float Vs[64][64];

    const int tid = threadIdx.x;
    const int tx = tid & 15;
    const int ty = tid >> 4;
    const int qi = blockIdx.x;
    const int bh = blockIdx.y;

    const float* Qb = Q + ((size_t)bh * Ssz + qi * 64) * DKsz;

#pragma unroll
    for (int q4 = 0; q4 < 4; q4++) {
        const int r  = (tid >> 4) + q4 * 16;
        const int d4 = (tid & 15) * 4;
        float4 qv = *(const float4*)(Qb + r * DKsz + d4);
        Qt[d4 + 0][r] = qv.x * 0.125f;
        Qt[d4 + 1][r] = qv.y * 0.125f;
        Qt[d4 + 2][r] = qv.z * 0.125f;
        Qt[d4 + 3][r] = qv.w * 0.125f;
    }

    float acc[4][4];
#pragma unroll
    for (int i = 0; i < 4; i++)
#pragma unroll
        for (int j = 0; j < 4; j++) acc[i][j] = 0.0f;
    float mrow[4], lrow[4];
#pragma unroll
    for (int i = 0; i < 4; i++) { mrow[i] = -INFINITY; lrow[i] = 0.0f; }

    for (int j = 0; j <= qi; j++) {
        __syncthreads();

        const float* Kb = K + ((size_t)bh * Ssz + j * 64) * DKsz;
        const float* Vb = V + ((size_t)bh * Ssz + j * 64) * DKsz;
#pragma unroll
        for (int q4 = 0; q4 < 4; q4++) {
            const int c  = (tid >> 4) + q4 * 16;
            const int d4 = (tid & 15) * 4;
            float4 kv = *(const float4*)(Kb + c * DKsz + d4);
            KtPt[d4 + 0][c] = kv.x;
            KtPt[d4 + 1][c] = kv.y;
            KtPt[d4 + 2][c] = kv.z;
            KtPt[d4 + 3][c] = kv.w;
        }
        {
            float4* Vs4 = (float4*)&Vs[0][0];
            const float4* Vb4 = (const float4*)Vb;
#pragma unroll
            for (int q4 = 0; q4 < 4; q4++)
                Vs4[tid + q4 * 256] = Vb4[tid + q4 * 256];
        }
        __syncthreads();

        float s[4][4];
#pragma unroll
        for (int i = 0; i < 4; i++)
#pragma unroll
            for (int jj = 0; jj < 4; jj++) s[i][jj] = 0.0f;
#pragma unroll 8
        for (int d = 0; d < 64; d++) {
            float a[4], b[4];
            *(float4*)a = *(const float4*)&Qt[d][ty * 4];
            *(float4*)b = *(const float4*)&KtPt[d][tx * 4];
#pragma unroll
            for (int i = 0; i < 4; i++)
#pragma unroll
                for (int jj = 0; jj < 4; jj++)
                    s[i][jj] += a[i] * b[jj];
        }

        if (j == qi) {
#pragma unroll
            for (int i = 0; i < 4; i++) {
                const int rg = ty * 4 + i;
#pragma unroll
                for (int jj = 0; jj < 4; jj++) {
                    const int cg = tx * 4 + jj;
                    if (cg > rg) s[i][jj] = -INFINITY;
                }
            }
        }

#pragma unroll
        for (int i = 0; i < 4; i++) {
            float mx = fmaxf(fmaxf(s[i][0], s[i][1]), fmaxf(s[i][2], s[i][3]));
#pragma unroll
            for (int o = 8; o >= 1; o >>= 1)
                mx = fmaxf(mx, __shfl_xor_sync(0xffffffffu, mx, o));
            const float mnew  = fmaxf(mrow[i], mx);
            const float alpha = __expf(mrow[i] - mnew);
            float sum = 0.0f;
#pragma unroll
            for (int jj = 0; jj < 4; jj++) {
                const float p = __expf(s[i][jj] - mnew);
                s[i][jj] = p;
                sum += p;
            }
#pragma unroll
            for (int o = 8; o >= 1; o >>= 1)
                sum += __shfl_xor_sync(0xffffffffu, sum, o);
            lrow[i] = lrow[i] * alpha + sum;
            mrow[i] = mnew;
#pragma unroll
            for (int jj = 0; jj < 4; jj++) acc[i][jj] *= alpha;
        }

        __syncthreads();

#pragma unroll
        for (int i = 0; i < 4; i++)
#pragma unroll
            for (int jj = 0; jj < 4; jj++)
                KtPt[tx * 4 + jj][ty * 4 + i] = s[i][jj];
        __syncthreads();

#pragma unroll 8
        for (int c = 0; c < 64; c++) {
            float a[4], b[4];
            *(float4*)a = *(const float4*)&KtPt[c][ty * 4];
            *(float4*)b = *(const float4*)&Vs[c][tx * 4];
#pragma unroll
            for (int i = 0; i < 4; i++)
#pragma unroll
                for (int jj = 0; jj < 4; jj++)
                    acc[i][jj] += a[i] * b[jj];
        }
    }

    const int b = bh >> 4;
    const int h = bh & 15;
#pragma unroll
    for (int i = 0; i < 4; i++) {
        const float inv = 1.0f / lrow[i];
        const int srow = qi * 64 + ty * 4 + i;
#pragma unroll
        for (int jj = 0; jj < 4; jj++) {
            const int dv = tx * 4 + jj;
            O[((size_t)b * Ssz + srow) * Dsz + h * DKsz + dv] = acc[i][jj] * inv;
        }
    }
}

// ---------------------------------------------------------------------------
extern "C" void kernel_launch(void* const* d_in, const int* in_sizes, int n_in,
                              void* d_out, int out_size)
{
    const float* q   = (const float*)d_in[0];
    const float* k   = (const float*)d_in[1];
    const float* v   = (const float*)d_in[2];
    // d_in[3] = mask (causal, handled analytically)
    const float* w_q = (const float*)d_in[4];
    const float* b_q = (const float*)d_in[5];
    const float* w_k = (const float*)d_in[6];
    const float* b_k = (const float*)d_in[7];
    const float* w_v = (const float*)d_in[8];
    const float* b_v = (const float*)d_in[9];
    const float* w_o = (const float*)d_in[10];
    const float* b_o = (const float*)d_in[11];
    float* out = (float*)d_out;

    float *qh, *kh, *vh, *att;
    cudaGetSymbolAddress((void**)&qh,  g_qh);
    cudaGetSymbolAddress((void**)&kh,  g_kh);
    cudaGetSymbolAddress((void**)&vh,  g_vh);
    cudaGetSymbolAddress((void**)&att, g_att);

    __nv_bfloat16 *qhi, *qlo, *khi, *klo, *vhi, *vlo, *ahi, *alo;
    __nv_bfloat16 *wqh, *wql, *wkh, *wkl, *wvh, *wvl, *woh, *wol;
    cudaGetSymbolAddress((void**)&qhi, g_q_hi);  cudaGetSymbolAddress((void**)&qlo, g_q_lo);
    cudaGetSymbolAddress((void**)&khi, g_k_hi);  cudaGetSymbolAddress((void**)&klo, g_k_lo);
    cudaGetSymbolAddress((void**)&vhi, g_v_hi);  cudaGetSymbolAddress((void**)&vlo, g_v_lo);
    cudaGetSymbolAddress((void**)&ahi, g_att_hi); cudaGetSymbolAddress((void**)&alo, g_att_lo);
    cudaGetSymbolAddress((void**)&wqh, g_wq_hi); cudaGetSymbolAddress((void**)&wql, g_wq_lo);
    cudaGetSymbolAddress((void**)&wkh, g_wk_hi); cudaGetSymbolAddress((void**)&wkl, g_wk_lo);
    cudaGetSymbolAddress((void**)&wvh, g_wv_hi); cudaGetSymbolAddress((void**)&wvl, g_wv_lo);
    cudaGetSymbolAddress((void**)&woh, g_wo_hi); cudaGetSymbolAddress((void**)&wol, g_wo_lo);

    cudaFuncSetAttribute(gemm_tc_kernel<0>,
                         cudaFuncAttributeMaxDynamicSharedMemorySize, GEMM_SMEM);
    cudaFuncSetAttribute(gemm_tc_kernel<1>,
                         cudaFuncAttributeMaxDynamicSharedMemorySize, GEMM_SMEM);

    const int nAct = Mtot * Ktot;   // 4M
    const int nW   = Dsz * Dsz;     // 1M
    dim3 bSplit(256);
    dim3 gAct((nAct / 4 + 255) / 256);
    dim3 gW((nW / 4 + 255) / 256);

    split_kernel<<<gAct, bSplit>>>(q, qhi, qlo, nAct / 4);
    split_kernel<<<gAct, bSplit>>>(k, khi, klo, nAct / 4);
    split_kernel<<<gAct, bSplit>>>(v, vhi, vlo, nAct / 4);
    split_kernel<<<gW, bSplit>>>(w_q, wqh, wql, nW / 4);
    split_kernel<<<gW, bSplit>>>(w_k, wkh, wkl, nW / 4);
    split_kernel<<<gW, bSplit>>>(w_v, wvh, wvl, nW / 4);
    split_kernel<<<gW, bSplit>>>(w_o, woh, wol, nW / 4);

    dim3 gGemm(Ntot / 128, Mtot / 128);  // (8, 32)
    gemm_tc_kernel<1><<<gGemm, 256, GEMM_SMEM>>>(qhi, qlo, wqh, wql, b_q, qh);
    gemm_tc_kernel<1><<<gGemm, 256, GEMM_SMEM>>>(khi, klo, wkh, wkl, b_k, kh);
    gemm_tc_kernel<1><<<gGemm, 256, GEMM_SMEM>>>(vhi, vlo, wvh, wvl, b_v, vh);

    dim3 gFlash(Ssz / 64, Bsz * Hsz);    // (32, 32)
    flash_attn_kernel<<<gFlash, 256>>>(qh, kh, vh, att);

    split_kernel<<<gAct, bSplit>>>(att, ahi, alo, nAct / 4);
    gemm_tc_kernel<0><<<gGemm, 256, GEMM_SMEM>>>(ahi, alo, woh, wol, b_o, out);
}

// round 9
// speedup vs baseline: 3.1171x; 2.1512x over previous
#include <cuda_runtime.h>
#include <cuda_bf16.h>
#include <math.h>
#include <stdint.h>

// Problem constants
#define Bsz  2
#define Ssz  2048
#define Dsz  1024
#define Hsz  16
#define DKsz 64
#define Mtot (Bsz * Ssz)   // 4096
#define Ntot Dsz           // 1024
#define Ktot Dsz           // 1024

// ---------------------------------------------------------------------------
// Scratch (device globals: allocation-free)
// ---------------------------------------------------------------------------
// input splits [M,K]
__device__ __nv_bfloat16 g_q_hi[Mtot * Ktot],  g_q_lo[Mtot * Ktot];
__device__ __nv_bfloat16 g_k_hi[Mtot * Ktot],  g_k_lo[Mtot * Ktot];
__device__ __nv_bfloat16 g_v_hi[Mtot * Ktot],  g_v_lo[Mtot * Ktot];
// head-layout projections [B,H,S,DK] (bf16 hi/lo, Q pre-scaled by 0.125)
__device__ __nv_bfloat16 g_qh_hi[Mtot * Ktot], g_qh_lo[Mtot * Ktot];
__device__ __nv_bfloat16 g_kh_hi[Mtot * Ktot], g_kh_lo[Mtot * Ktot];
__device__ __nv_bfloat16 g_vh_hi[Mtot * Ktot], g_vh_lo[Mtot * Ktot];
// attention output [B,S,D]
__device__ __nv_bfloat16 g_att_hi[Mtot * Ktot], g_att_lo[Mtot * Ktot];
// weight splits
__device__ __nv_bfloat16 g_wq_hi[Dsz * Dsz], g_wq_lo[Dsz * Dsz];
__device__ __nv_bfloat16 g_wk_hi[Dsz * Dsz], g_wk_lo[Dsz * Dsz];
__device__ __nv_bfloat16 g_wv_hi[Dsz * Dsz], g_wv_lo[Dsz * Dsz];
__device__ __nv_bfloat16 g_wo_hi[Dsz * Dsz], g_wo_lo[Dsz * Dsz];

// ---------------------------------------------------------------------------
// Helpers
// ---------------------------------------------------------------------------
__device__ __forceinline__ uint32_t smem_to_u32(const void* smem_ptr) {
    uint32_t addr;
    asm("{ .reg .u64 tmp; cvta.to.shared.u64 tmp, %1; cvt.u32.u64 %0, tmp; }"
        : "=r"(addr) : "l"(smem_ptr));
    return addr;
}

__device__ __forceinline__ void cp_async16(uint32_t dst, const void* src) {
    asm volatile("cp.async.cg.shared.global [%0], [%1], 16;" :: "r"(dst), "l"(src));
}
__device__ __forceinline__ void cp_async_commit() {
    asm volatile("cp.async.commit_group;");
}
template <int N>
__device__ __forceinline__ void cp_async_wait() {
    asm volatile("cp.async.wait_group %0;" :: "n"(N));
}

__device__ __forceinline__ void ldsm_x4(uint32_t& r0, uint32_t& r1, uint32_t& r2,
                                        uint32_t& r3, uint32_t addr) {
    asm volatile("ldmatrix.sync.aligned.m8n8.x4.shared.b16 {%0,%1,%2,%3}, [%4];"
                 : "=r"(r0), "=r"(r1), "=r"(r2), "=r"(r3) : "r"(addr));
}
__device__ __forceinline__ void ldsm_x4_trans(uint32_t& r0, uint32_t& r1, uint32_t& r2,
                                              uint32_t& r3, uint32_t addr) {
    asm volatile("ldmatrix.sync.aligned.m8n8.x4.trans.shared.b16 {%0,%1,%2,%3}, [%4];"
                 : "=r"(r0), "=r"(r1), "=r"(r2), "=r"(r3) : "r"(addr));
}

__device__ __forceinline__ void mma16816(float* d,
                                         uint32_t a0, uint32_t a1, uint32_t a2, uint32_t a3,
                                         uint32_t b0, uint32_t b1) {
    asm volatile(
        "mma.sync.aligned.m16n8k16.row.col.f32.bf16.bf16.f32 "
        "{%0,%1,%2,%3}, {%4,%5,%6,%7}, {%8,%9}, {%0,%1,%2,%3};"
        : "+f"(d[0]), "+f"(d[1]), "+f"(d[2]), "+f"(d[3])
        : "r"(a0), "r"(a1), "r"(a2), "r"(a3), "r"(b0), "r"(b1));
}

// split two floats into packed bf16x2 hi + lo(residual)
__device__ __forceinline__ void split2(float x, float y, uint32_t& h, uint32_t& l) {
    __nv_bfloat162 hh = __floats2bfloat162_rn(x, y);
    float rx = x - __bfloat162float(hh.x);
    float ry = y - __bfloat162float(hh.y);
    __nv_bfloat162 ll = __floats2bfloat162_rn(rx, ry);
    h = *(uint32_t*)&hh;
    l = *(uint32_t*)&ll;
}

// ---------------------------------------------------------------------------
// fp32 -> (hi, lo) bf16 split
// ---------------------------------------------------------------------------
__global__ void split_kernel(const float* __restrict__ x,
                             __nv_bfloat16* __restrict__ hi,
                             __nv_bfloat16* __restrict__ lo, int n4)
{
    int i = blockIdx.x * blockDim.x + threadIdx.x;
    if (i >= n4) return;
    float4 v = ((const float4*)x)[i];
    uint32_t h0, l0, h1, l1;
    split2(v.x, v.y, h0, l0);
    split2(v.z, v.w, h1, l1);
    ((uint32_t*)hi)[i * 2 + 0] = h0;
    ((uint32_t*)hi)[i * 2 + 1] = h1;
    ((uint32_t*)lo)[i * 2 + 0] = l0;
    ((uint32_t*)lo)[i * 2 + 1] = l1;
}

// ---------------------------------------------------------------------------
// bf16x3 GEMM via mma.sync: out[M,N] = A[M,K] @ B[N,K]^T + bias
// MODE 0: fp32 [M,N] output. MODE 1: bf16 hi/lo head-scatter output w/ scale.
// ---------------------------------------------------------------------------
#define BK 32
#define NC (Ktot / BK)                 // 32 chunks
#define TILE_B (128 * BK * 2)          // 8192 bytes per bf16 tile
#define BUF_B  (4 * TILE_B)            // Ahi, Alo, Bhi, Blo = 32 KB
#define GEMM_SMEM (2 * BUF_B)          // 64 KB

__device__ __forceinline__ uint32_t sw_off(int row, int c) {
    return (uint32_t)(row * 64 + ((c ^ ((row >> 1) & 3)) << 4));
}

__device__ __forceinline__ void prefetch_chunk(
    uint32_t sbase, int buf,
    const __nv_bfloat16* Ahi, const __nv_bfloat16* Alo,
    const __nv_bfloat16* Bhi, const __nv_bfloat16* Blo,
    int bm, int bn, int k0, int tid)
{
    const __nv_bfloat16* srcs[4] = { Ahi, Alo, Bhi, Blo };
    const int r0[4] = { bm, bm, bn, bn };
    uint32_t base = sbase + buf * BUF_B;
#pragma unroll
    for (int t = 0; t < 4; t++) {
#pragma unroll
        for (int it = 0; it < 2; it++) {
            int seg = tid + it * 256;          // 0..511
            int row = seg >> 2;                // 0..127
            int c   = seg & 3;                 // 16B chunk
            const void* src = srcs[t] + (size_t)(r0[t] + row) * Ktot + k0 + c * 8;
            cp_async16(base + t * TILE_B + sw_off(row, c), src);
        }
    }
}

template <int MODE>
__global__ __launch_bounds__(256, 2) void gemm_tc_kernel(
    const __nv_bfloat16* __restrict__ Ahi, const __nv_bfloat16* __restrict__ Alo,
    const __nv_bfloat16* __restrict__ Bhi, const __nv_bfloat16* __restrict__ Blo,
    const float* __restrict__ bias, float* __restrict__ outF,
    __nv_bfloat16* __restrict__ outH, __nv_bfloat16* __restrict__ outL, float scale)
{
    extern __shared__ __align__(128) char smem[];
    const uint32_t sbase = smem_to_u32(smem);

    const int tid = threadIdx.x;
    const int wid = tid >> 5;
    const int lid = tid & 31;
    const int wr = wid >> 2;          // 0..1
    const int wc = wid & 3;           // 0..3
    const int bm = blockIdx.y * 128;
    const int bn = blockIdx.x * 128;

    float acc[4][4][4];
#pragma unroll
    for (int mi = 0; mi < 4; mi++)
#pragma unroll
        for (int ni = 0; ni < 4; ni++)
#pragma unroll
            for (int r = 0; r < 4; r++) acc[mi][ni][r] = 0.0f;

    prefetch_chunk(sbase, 0, Ahi, Alo, Bhi, Blo, bm, bn, 0, tid);
    cp_async_commit();

    for (int c = 0; c < NC; c++) {
        if (c + 1 < NC) {
            prefetch_chunk(sbase, (c + 1) & 1, Ahi, Alo, Bhi, Blo,
                           bm, bn, (c + 1) * BK, tid);
            cp_async_commit();
            cp_async_wait<1>();
        } else {
            cp_async_wait<0>();
        }
        __syncthreads();

        const uint32_t buf = sbase + (c & 1) * BUF_B;
        const uint32_t sAhi = buf + 0 * TILE_B;
        const uint32_t sAlo = buf + 1 * TILE_B;
        const uint32_t sBhi = buf + 2 * TILE_B;
        const uint32_t sBlo = buf + 3 * TILE_B;

#pragma unroll
        for (int ks = 0; ks < 2; ks++) {
            uint32_t bh[4][2], bl[4][2];
#pragma unroll
            for (int p = 0; p < 2; p++) {
                const int nrow = wc * 32 + p * 16 + (lid & 15);
                const int kc = ks * 2 + (lid >> 4);
                uint32_t r0, r1, r2, r3;
                ldsm_x4(r0, r1, r2, r3, sBhi + sw_off(nrow, kc));
                bh[p * 2][0] = r0; bh[p * 2 + 1][0] = r1;
                bh[p * 2][1] = r2; bh[p * 2 + 1][1] = r3;
                ldsm_x4(r0, r1, r2, r3, sBlo + sw_off(nrow, kc));
                bl[p * 2][0] = r0; bl[p * 2 + 1][0] = r1;
                bl[p * 2][1] = r2; bl[p * 2 + 1][1] = r3;
            }
#pragma unroll
            for (int mi = 0; mi < 4; mi++) {
                const int mrow = wr * 64 + mi * 16 + (lid & 15);
                const int kc = ks * 2 + (lid >> 4);
                uint32_t ah0, ah1, ah2, ah3, al0, al1, al2, al3;
                ldsm_x4(ah0, ah1, ah2, ah3, sAhi + sw_off(mrow, kc));
                ldsm_x4(al0, al1, al2, al3, sAlo + sw_off(mrow, kc));
#pragma unroll
                for (int ni = 0; ni < 4; ni++) {
                    float* d = acc[mi][ni];
                    mma16816(d, ah0, ah1, ah2, ah3, bh[ni][0], bh[ni][1]);
                    mma16816(d, ah0, ah1, ah2, ah3, bl[ni][0], bl[ni][1]);
                    mma16816(d, al0, al1, al2, al3, bh[ni][0], bh[ni][1]);
                }
            }
        }
        __syncthreads();
    }

#pragma unroll
    for (int mi = 0; mi < 4; mi++) {
#pragma unroll
        for (int ni = 0; ni < 4; ni++) {
#pragma unroll
            for (int half = 0; half < 2; half++) {
                const int m = bm + wr * 64 + mi * 16 + (lid >> 2) + half * 8;
                const int n = bn + wc * 32 + ni * 8 + 2 * (lid & 3);
                float v0 = acc[mi][ni][half * 2 + 0] + bias[n];
                float v1 = acc[mi][ni][half * 2 + 1] + bias[n + 1];
                if (MODE == 0) {
                    *(float2*)&outF[(size_t)m * Ntot + n] = make_float2(v0, v1);
                } else {
                    v0 *= scale; v1 *= scale;
                    uint32_t h, l;
                    split2(v0, v1, h, l);
                    const int b  = m >> 11;
                    const int s  = m & 2047;
                    const int hh = n >> 6;
                    const int dk = n & 63;
                    const size_t idx = (((size_t)(b * Hsz + hh) * Ssz) + s) * DKsz + dk;
                    *(uint32_t*)&outH[idx] = h;
                    *(uint32_t*)&outL[idx] = l;
                }
            }
        }
    }
}

// ---------------------------------------------------------------------------
// Flash attention via mma.sync bf16x3. Causal.
// 128 threads (4 warps), BQ=64 (16 rows/warp), BKV=64, DK=64.
// smem: Q hi/lo (16KB) + double-buffered K/V hi/lo (64KB) = 80KB.
// Rows are 64 bf16 = 128B, swizzle chunk c ^= (row&7) -> conflict-free ldmatrix.
// ---------------------------------------------------------------------------
#define FA_TILE 8192                   // one 64x64 bf16 tile
#define FA_KVBUF (4 * FA_TILE)         // KH, KL, VH, VL
#define FA_SMEM (2 * FA_TILE + 2 * FA_KVBUF)   // 80 KB

__device__ __forceinline__ uint32_t fa_sw(int row, int c) {
    return (uint32_t)(row * 128 + ((c ^ (row & 7)) << 4));
}

__device__ __forceinline__ void fa_prefetch_kv(
    uint32_t dstbase,
    const __nv_bfloat16* KH, const __nv_bfloat16* KL,
    const __nv_bfloat16* VH, const __nv_bfloat16* VL,
    size_t gbase, int tid)
{
    const __nv_bfloat16* srcs[4] = { KH, KL, VH, VL };
#pragma unroll
    for (int t = 0; t < 4; t++) {
#pragma unroll
        for (int it = 0; it < 4; it++) {
            int seg = tid + it * 128;      // 0..511
            int row = seg >> 3;
            int c   = seg & 7;
            cp_async16(dstbase + t * FA_TILE + fa_sw(row, c),
                       srcs[t] + gbase + (size_t)row * DKsz + c * 8);
        }
    }
}

__global__ __launch_bounds__(128, 2) void flash_mma_kernel(
    const __nv_bfloat16* __restrict__ QHI, const __nv_bfloat16* __restrict__ QLO,
    const __nv_bfloat16* __restrict__ KHI, const __nv_bfloat16* __restrict__ KLO,
    const __nv_bfloat16* __restrict__ VHI, const __nv_bfloat16* __restrict__ VLO,
    __nv_bfloat16* __restrict__ OHI, __nv_bfloat16* __restrict__ OLO)
{
    extern __shared__ __align__(128) char smem[];
    const uint32_t sb = smem_to_u32(smem);
    const int tid = threadIdx.x;
    const int wid = tid >> 5;
    const int lid = tid & 31;
    const int qi = gridDim.x - 1 - blockIdx.x;   // heavy tiles first
    const int bh = blockIdx.y;

    // ---- load Q hi/lo tiles ----
    const size_t qbase = ((size_t)bh * Ssz + qi * 64) * DKsz;
    {
        const __nv_bfloat16* srcs[2] = { QHI, QLO };
#pragma unroll
        for (int t = 0; t < 2; t++) {
#pragma unroll
            for (int it = 0; it < 4; it++) {
                int seg = tid + it * 128;
                int row = seg >> 3;
                int c   = seg & 7;
                cp_async16(sb + t * FA_TILE + fa_sw(row, c),
                           srcs[t] + qbase + (size_t)row * DKsz + c * 8);
            }
        }
    }
    cp_async_commit();
    // prefetch KV block 0
    const uint32_t kvbase = sb + 2 * FA_TILE;
    fa_prefetch_kv(kvbase, KHI, KLO, VHI, VLO, ((size_t)bh * Ssz) * DKsz, tid);
    cp_async_commit();
    cp_async_wait<0>();
    __syncthreads();

    // ---- Q fragments (register resident) ----
    uint32_t qfh[4][4], qfl[4][4];
#pragma unroll
    for (int t = 0; t < 4; t++) {
        const int row = wid * 16 + (lid & 15);
        const int c = t * 2 + (lid >> 4);
        const uint32_t off = fa_sw(row, c);
        ldsm_x4(qfh[t][0], qfh[t][1], qfh[t][2], qfh[t][3], sb + off);
        ldsm_x4(qfl[t][0], qfl[t][1], qfl[t][2], qfl[t][3], sb + FA_TILE + off);
    }

    float o[8][4];
#pragma unroll
    for (int n = 0; n < 8; n++)
#pragma unroll
        for (int r = 0; r < 4; r++) o[n][r] = 0.0f;
    float mA = -INFINITY, mB = -INFINITY, lA = 0.0f, lB = 0.0f;

    const int rowA = qi * 64 + wid * 16 + (lid >> 2);
    const int rowB = rowA + 8;

    for (int j = 0; j <= qi; j++) {
        if (j < qi) {
            fa_prefetch_kv(kvbase + ((j + 1) & 1) * FA_KVBUF, KHI, KLO, VHI, VLO,
                           ((size_t)bh * Ssz + (j + 1) * 64) * DKsz, tid);
            cp_async_commit();
            cp_async_wait<1>();
        } else {
            cp_async_wait<0>();
        }
        __syncthreads();

        const uint32_t kb = kvbase + (j & 1) * FA_KVBUF;

        // ---- S = Q K^T (bf16x3) ----
        float s[8][4];
#pragma unroll
        for (int n = 0; n < 8; n++)
#pragma unroll
            for (int r = 0; r < 4; r++) s[n][r] = 0.0f;

#pragma unroll
        for (int t = 0; t < 4; t++) {
#pragma unroll
            for (int p = 0; p < 4; p++) {
                const int row = p * 16 + (lid & 15);
                const int c = t * 2 + (lid >> 4);
                const uint32_t off = fa_sw(row, c);
                uint32_t kh0, kh1, kh2, kh3, kl0, kl1, kl2, kl3;
                ldsm_x4(kh0, kh1, kh2, kh3, kb + off);             // K_hi
                ldsm_x4(kl0, kl1, kl2, kl3, kb + FA_TILE + off);   // K_lo
                mma16816(s[2 * p],     qfh[t][0], qfh[t][1], qfh[t][2], qfh[t][3], kh0, kh2);
                mma16816(s[2 * p + 1], qfh[t][0], qfh[t][1], qfh[t][2], qfh[t][3], kh1, kh3);
                mma16816(s[2 * p],     qfh[t][0], qfh[t][1], qfh[t][2], qfh[t][3], kl0, kl2);
                mma16816(s[2 * p + 1], qfh[t][0], qfh[t][1], qfh[t][2], qfh[t][3], kl1, kl3);
                mma16816(s[2 * p],     qfl[t][0], qfl[t][1], qfl[t][2], qfl[t][3], kh0, kh2);
                mma16816(s[2 * p + 1], qfl[t][0], qfl[t][1], qfl[t][2], qfl[t][3], kh1, kh3);
            }
        }

        // ---- causal mask (diagonal block only) ----
        if (j == qi) {
#pragma unroll
            for (int n = 0; n < 8; n++) {
                const int col = qi * 64 + n * 8 + 2 * (lid & 3);
                if (col > rowA)     s[n][0] = -INFINITY;
                if (col + 1 > rowA) s[n][1] = -INFINITY;
                if (col > rowB)     s[n][2] = -INFINITY;
                if (col + 1 > rowB) s[n][3] = -INFINITY;
            }
        }

        // ---- online softmax ----
        float mxA = -INFINITY, mxB = -INFINITY;
#pragma unroll
        for (int n = 0; n < 8; n++) {
            mxA = fmaxf(mxA, fmaxf(s[n][0], s[n][1]));
            mxB = fmaxf(mxB, fmaxf(s[n][2], s[n][3]));
        }
        mxA = fmaxf(mxA, __shfl_xor_sync(0xffffffffu, mxA, 1));
        mxA = fmaxf(mxA, __shfl_xor_sync(0xffffffffu, mxA, 2));
        mxB = fmaxf(mxB, __shfl_xor_sync(0xffffffffu, mxB, 1));
        mxB = fmaxf(mxB, __shfl_xor_sync(0xffffffffu, mxB, 2));

        const float mnA = fmaxf(mA, mxA);
        const float mnB = fmaxf(mB, mxB);
        const float aA = __expf(mA - mnA);
        const float aB = __expf(mB - mnB);
        float sumA = 0.0f, sumB = 0.0f;
#pragma unroll
        for (int n = 0; n < 8; n++) {
            s[n][0] = __expf(s[n][0] - mnA);
            s[n][1] = __expf(s[n][1] - mnA);
            s[n][2] = __expf(s[n][2] - mnB);
            s[n][3] = __expf(s[n][3] - mnB);
            sumA += s[n][0] + s[n][1];
            sumB += s[n][2] + s[n][3];
        }
        sumA += __shfl_xor_sync(0xffffffffu, sumA, 1);
        sumA += __shfl_xor_sync(0xffffffffu, sumA, 2);
        sumB += __shfl_xor_sync(0xffffffffu, sumB, 1);
        sumB += __shfl_xor_sync(0xffffffffu, sumB, 2);
        lA = lA * aA + sumA;
        lB = lB * aB + sumB;
        mA = mnA; mB = mnB;
#pragma unroll
        for (int n = 0; n < 8; n++) {
            o[n][0] *= aA; o[n][1] *= aA;
            o[n][2] *= aB; o[n][3] *= aB;
        }

        // ---- O += P V (bf16x3) ----
#pragma unroll
        for (int t = 0; t < 4; t++) {
            // P fragments for kv k-step t (tiles 2t, 2t+1)
            uint32_t ph[4], pl[4];
            split2(s[2 * t][0],     s[2 * t][1],     ph[0], pl[0]);
            split2(s[2 * t][2],     s[2 * t][3],     ph[1], pl[1]);
            split2(s[2 * t + 1][0], s[2 * t + 1][1], ph[2], pl[2]);
            split2(s[2 * t + 1][2], s[2 * t + 1][3], ph[3], pl[3]);
#pragma unroll
            for (int dp = 0; dp < 4; dp++) {
                const int row = t * 16 + (lid & 15);
                const int c = dp * 2 + (lid >> 4);
                const uint32_t off = fa_sw(row, c);
                uint32_t vh0, vh1, vh2, vh3, vl0, vl1, vl2, vl3;
                ldsm_x4_trans(vh0, vh1, vh2, vh3, kb + 2 * FA_TILE + off);  // V_hi
                ldsm_x4_trans(vl0, vl1, vl2, vl3, kb + 3 * FA_TILE + off);  // V_lo
                mma16816(o[2 * dp],     ph[0], ph[1], ph[2], ph[3], vh0, vh1);
                mma16816(o[2 * dp + 1], ph[0], ph[1], ph[2], ph[3], vh2, vh3);
                mma16816(o[2 * dp],     ph[0], ph[1], ph[2], ph[3], vl0, vl1);
                mma16816(o[2 * dp + 1], ph[0], ph[1], ph[2], ph[3], vl2, vl3);
                mma16816(o[2 * dp],     pl[0], pl[1], pl[2], pl[3], vh0, vh1);
                mma16816(o[2 * dp + 1], pl[0], pl[1], pl[2], pl[3], vh2, vh3);
            }
        }
        __syncthreads();   // done reading this KV buffer
    }

    // ---- epilogue: normalize, split, write att hi/lo [B,S,D] ----
    const float invA = 1.0f / lA;
    const float invB = 1.0f / lB;
    const int b = bh >> 4;
    const int h = bh & 15;
    const int sA = qi * 64 + wid * 16 + (lid >> 2);
#pragma unroll
    for (int n = 0; n < 8; n++) {
        const int col = h * DKsz + n * 8 + 2 * (lid & 3);
        uint32_t hi0, lo0, hi1, lo1;
        split2(o[n][0] * invA, o[n][1] * invA, hi0, lo0);
        split2(o[n][2] * invB, o[n][3] * invB, hi1, lo1);
        const size_t iA = ((size_t)b * Ssz + sA) * Dsz + col;
        const size_t iB = ((size_t)b * Ssz + sA + 8) * Dsz + col;
        *(uint32_t*)&OHI[iA] = hi0;  *(uint32_t*)&OLO[iA] = lo0;
        *(uint32_t*)&OHI[iB] = hi1;  *(uint32_t*)&OLO[iB] = lo1;
    }
}

// ---------------------------------------------------------------------------
extern "C" void kernel_launch(void* const* d_in, const int* in_sizes, int n_in,
                              void* d_out, int out_size)
{
    const float* q   = (const float*)d_in[0];
    const float* k   = (const float*)d_in[1];
    const float* v   = (const float*)d_in[2];
    // d_in[3] = mask (causal, handled analytically)
    const float* w_q = (const float*)d_in[4];
    const float* b_q = (const float*)d_in[5];
    const float* w_k = (const float*)d_in[6];
    const float* b_k = (const float*)d_in[7];
    const float* w_v = (const float*)d_in[8];
    const float* b_v = (const float*)d_in[9];
    const float* w_o = (const float*)d_in[10];
    const float* b_o = (const float*)d_in[11];
    float* out = (float*)d_out;

    __nv_bfloat16 *qhi, *qlo, *khi, *klo, *vhi, *vlo;
    __nv_bfloat16 *qhh, *qhl, *khh, *khl, *vhh, *vhl, *ahi, *alo;
    __nv_bfloat16 *wqh, *wql, *wkh, *wkl, *wvh, *wvl, *woh, *wol;
    cudaGetSymbolAddress((void**)&qhi, g_q_hi);   cudaGetSymbolAddress((void**)&qlo, g_q_lo);
    cudaGetSymbolAddress((void**)&khi, g_k_hi);   cudaGetSymbolAddress((void**)&klo, g_k_lo);
    cudaGetSymbolAddress((void**)&vhi, g_v_hi);   cudaGetSymbolAddress((void**)&vlo, g_v_lo);
    cudaGetSymbolAddress((void**)&qhh, g_qh_hi);  cudaGetSymbolAddress((void**)&qhl, g_qh_lo);
    cudaGetSymbolAddress((void**)&khh, g_kh_hi);  cudaGetSymbolAddress((void**)&khl, g_kh_lo);
    cudaGetSymbolAddress((void**)&vhh, g_vh_hi);  cudaGetSymbolAddress((void**)&vhl, g_vh_lo);
    cudaGetSymbolAddress((void**)&ahi, g_att_hi); cudaGetSymbolAddress((void**)&alo, g_att_lo);
    cudaGetSymbolAddress((void**)&wqh, g_wq_hi);  cudaGetSymbolAddress((void**)&wql, g_wq_lo);
    cudaGetSymbolAddress((void**)&wkh, g_wk_hi);  cudaGetSymbolAddress((void**)&wkl, g_wk_lo);
    cudaGetSymbolAddress((void**)&wvh, g_wv_hi);  cudaGetSymbolAddress((void**)&wvl, g_wv_lo);
    cudaGetSymbolAddress((void**)&woh, g_wo_hi);  cudaGetSymbolAddress((void**)&wol, g_wo_lo);

    cudaFuncSetAttribute(gemm_tc_kernel<0>,
                         cudaFuncAttributeMaxDynamicSharedMemorySize, GEMM_SMEM);
    cudaFuncSetAttribute(gemm_tc_kernel<1>,
                         cudaFuncAttributeMaxDynamicSharedMemorySize, GEMM_SMEM);
    cudaFuncSetAttribute(flash_mma_kernel,
                         cudaFuncAttributeMaxDynamicSharedMemorySize, FA_SMEM);

    const int nAct = Mtot * Ktot;   // 4M
    const int nW   = Dsz * Dsz;     // 1M
    dim3 bSplit(256);
    dim3 gAct((nAct / 4 + 255) / 256);
    dim3 gW((nW / 4 + 255) / 256);

    split_kernel<<<gAct, bSplit>>>(q, qhi, qlo, nAct / 4);
    split_kernel<<<gAct, bSplit>>>(k, khi, klo, nAct / 4);
    split_kernel<<<gAct, bSplit>>>(v, vhi, vlo, nAct / 4);
    split_kernel<<<gW, bSplit>>>(w_q, wqh, wql, nW / 4);
    split_kernel<<<gW, bSplit>>>(w_k, wkh, wkl, nW / 4);
    split_kernel<<<gW, bSplit>>>(w_v, wvh, wvl, nW / 4);
    split_kernel<<<gW, bSplit>>>(w_o, woh, wol, nW / 4);

    dim3 gGemm(Ntot / 128, Mtot / 128);  // (8, 32)
    gemm_tc_kernel<1><<<gGemm, 256, GEMM_SMEM>>>(qhi, qlo, wqh, wql, b_q,
                                                 nullptr, qhh, qhl, 0.125f);
    gemm_tc_kernel<1><<<gGemm, 256, GEMM_SMEM>>>(khi, klo, wkh, wkl, b_k,
                                                 nullptr, khh, khl, 1.0f);
    gemm_tc_kernel<1><<<gGemm, 256, GEMM_SMEM>>>(vhi, vlo, wvh, wvl, b_v,
                                                 nullptr, vhh, vhl, 1.0f);

    dim3 gFlash(Ssz / 64, Bsz * Hsz);    // (32, 32)
    flash_mma_kernel<<<gFlash, 128, FA_SMEM>>>(qhh, qhl, khh, khl, vhh, vhl, ahi, alo);

    gemm_tc_kernel<0><<<gGemm, 256, GEMM_SMEM>>>(ahi, alo, woh, wol, b_o,
                                                 out, nullptr, nullptr, 1.0f);
}